// round 12
// baseline (speedup 1.0000x reference)
#include <cuda_runtime.h>
#include <cstdint>

#define NXX 64
#define DTT 1e-4f

__device__ __forceinline__ float tanh_approx(float x) {
    float t;
    asm("tanh.approx.f32 %0, %1;" : "=f"(t) : "f"(x));
    return t;
}
__device__ __forceinline__ uint64_t pack2(float lo, float hi) {
    uint64_t r;
    asm("mov.b64 %0, {%1, %2};" : "=l"(r) : "f"(lo), "f"(hi));
    return r;
}
__device__ __forceinline__ void unpack2(uint64_t v, float& lo, float& hi) {
    asm("mov.b64 {%0, %1}, %2;" : "=f"(lo), "=f"(hi) : "l"(v));
}
__device__ __forceinline__ uint64_t fma2(uint64_t a, uint64_t b, uint64_t c) {
    uint64_t d;
    asm("fma.rn.f32x2 %0, %1, %2, %3;" : "=l"(d) : "l"(a), "l"(b), "l"(c));
    return d;
}
__device__ __forceinline__ uint64_t add2(uint64_t a, uint64_t b) {
    uint64_t d;
    asm("add.rn.f32x2 %0, %1, %2;" : "=l"(d) : "l"(a), "l"(b));
    return d;
}

// 256 threads, 4 lanes/point (p = tid>>2, s = tid&3), 2 warps per SMSP.
// R10 retried WITH the R11 shfl-free reduce: per-warp stream is ~45 instr,
// so each warp's LDS/recon/z/acc/store segments interleave with the other
// warp's MUFU drain (16 tanh-instr/SMSP = 128-cyc floor, unchanged).
//
// SHFL-FREE REDUCE: un = base + P0+P1+P2+P3; lane s stores its partial into
// component s of a per-point float4 (lane 0 folds base: stores base+P0).
// One 4-byte STS per lane (conflict-free), then straight to the barrier.
// Consumers load each needed point with one LDS.128 (broadcast across the
// 4 lanes of a point) and reconstruct u = (x+y)+(z+w) — identical op order
// in every lane, so the dynamics stay bitwise consistent.
//
// Boundary (p=0,63): Cq=0 and base=0 => un==0, no select on the store path.
// Stencil folded into weights (f64 at init): z = Wuc*uc + Wp*up + Wm*um + B,
//   Wp = 31.5*Wg + 3969*Wl, Wm = -31.5*Wg + 3969*Wl, Wuc = Wu - 7938*Wl.
// Head folded: Cq = gamma*DT*wc, Kc = gamma*DT*bc.
__global__ __launch_bounds__(256, 1) void scct_kernel(
    const float* __restrict__ u0,  const float* __restrict__ w1,
    const float* __restrict__ b1,  const float* __restrict__ w2,
    const float* __restrict__ b2,  const float* __restrict__ wc,
    const float* __restrict__ bc,  const float* __restrict__ gamma_p,
    const int*   __restrict__ nt_p, float* __restrict__ out)
{
    __shared__ float4 ub4[2][NXX];   // {base+P0, P1, P2, P3} per point

    const int tid = threadIdx.x;
    const int p = tid >> 2;   // grid point 0..63
    const int s = tid & 3;    // hidden-unit sub-slot

    const float* wsel = (s < 2) ? w1 : w2;
    const float* bsel = (s < 2) ? b1 : b2;
    const int jbase = (s & 1) * 8;

    const float gmm = *gamma_p;
    const float gdt = gmm * DTT;
    const bool interior = (p > 0) && (p < NXX - 1);

    uint64_t Wp2[4], Wm2[4], Wuc2[4], Bq2[4], Cq2[4];
#pragma unroll
    for (int j = 0; j < 4; j++) {
        float pl[2], ml[2], ul[2], bl[2], cl[2];
#pragma unroll
        for (int h = 0; h < 2; h++) {
            int q = jbase + 2 * j + h;          // row within selected layer
            int m = s * 8 + 2 * j + h;          // index into wc (0..31)
            double Wu = (double)wsel[q * 3 + 0];
            double Wg = (double)wsel[q * 3 + 1];
            double Wl = (double)wsel[q * 3 + 2];
            if (interior) {
                pl[h] = (float)( 31.5 * Wg + 3969.0 * Wl);
                ml[h] = (float)(-31.5 * Wg + 3969.0 * Wl);
                ul[h] = (float)(Wu - 7938.0 * Wl);
                cl[h] = gdt * wc[m];
            } else {
                pl[h] = 0.0f;
                ml[h] = 0.0f;
                ul[h] = (float)Wu;
                cl[h] = 0.0f;              // boundary: P contributions vanish
            }
            bl[h] = bsel[q];
        }
        Wp2[j]  = pack2(pl[0], pl[1]);
        Wm2[j]  = pack2(ml[0], ml[1]);
        Wuc2[j] = pack2(ul[0], ul[1]);
        Bq2[j]  = pack2(bl[0], bl[1]);
        Cq2[j]  = pack2(cl[0], cl[1]);
    }
    const float Kc = gdt * (*bc);
    const int Nt = *nt_p;

    if (tid < NXX) {
        float v = u0[tid];
        ub4[0][tid] = make_float4(v, 0.0f, 0.0f, 0.0f);  // quad form of u0
    }
    __syncthreads();

    const float INVDX2 = 3969.0f;  // 63^2

    const int pm = (p == 0) ? 0 : p - 1;
    const int pp = (p == NXX - 1) ? NXX - 1 : p + 1;

    int cur = 0;

    for (int it = 0; it < Nt; ++it) {
        // ---- chain head: 3 pipelined LDS.128 (broadcast within point) ----
        const float4 m4 = ub4[cur][pm];
        const float4 p4 = ub4[cur][pp];
        const float4 c4 = ub4[cur][p];

        // reconstruct u (depth-2 adds; identical op order in every lane)
        const float um = (m4.x + m4.y) + (m4.z + m4.w);
        const float up = (p4.x + p4.y) + (p4.z + p4.w);
        const float uc = (c4.x + c4.y) + (c4.z + c4.w);

        const uint64_t um2 = pack2(um, um);
        const uint64_t up2 = pack2(up, up);
        const uint64_t uc2 = pack2(uc, uc);

        // ---- MLP: 4 f32x2 pairs, 3-term z, 2 independent acc chains ----
        uint64_t A0 = 0ull, A1 = 0ull;
#pragma unroll
        for (int j = 0; j < 4; j++) {
            uint64_t z2 = fma2(Wuc2[j], uc2,
                          fma2(Wp2[j], up2,
                          fma2(Wm2[j], um2, Bq2[j])));
            float zl, zh;
            unpack2(z2, zl, zh);
            uint64_t t2 = pack2(tanh_approx(zl), tanh_approx(zh));
            if (j & 1) A1 = fma2(Cq2[j], t2, A1);
            else       A0 = fma2(Cq2[j], t2, A0);
        }
        float al, ah;
        unpack2(add2(A0, A1), al, ah);
        float Ppart = al + ah;            // this lane's partial head sum

        // base (computed by all lanes; overlaps the MUFU stream)
        const float lx   = ((up - 2.0f * uc) + um) * INVDX2;
        const float cb   = fmaf(0.5f, uc, -(uc * uc * uc));
        const float core = fmaf(0.8f, lx, cb);
        const float base = interior ? (fmaf(DTT, core, uc) + Kc) : 0.0f;

        if (s == 0) Ppart += base;        // lane 0 folds base into its slot

        // ---- store own 4-byte component, NO reduce before the barrier ----
        reinterpret_cast<float*>(&ub4[cur ^ 1][p])[s] = Ppart;
        __syncthreads();

        cur ^= 1;
    }

    // ---- epilogue: reconstruct u, then phi2 + histogram entropy ----
    __shared__ float uf[NXX];
    if (tid < NXX) {
        float4 v = ub4[cur][tid];
        float u = (v.x + v.y) + (v.z + v.w);
        uf[tid] = u;
        out[tid] = u;
    }
    __syncthreads();

    if (tid == 0) {
        float s2 = 0.0f, vmax = 0.0f;
        for (int i = 0; i < NXX; i++) {
            float u = uf[i];
            s2 += u * u;
            vmax = fmaxf(vmax, fabsf(u));
        }
        float phi2 = s2 * (1.0f / 64.0f);

        int hist[64];
#pragma unroll
        for (int i = 0; i < 64; i++) hist[i] = 0;
        float denom = fmaxf(vmax, 1e-12f);
        for (int i = 0; i < NXX; i++) {
            float vn = fabsf(uf[i]) / denom;   // IEEE div, matches ref
            int b = (int)(vn * 64.0f);
            if (b > 63) b = 63;
            hist[b]++;
        }
        float H = 0.0f;
        for (int i = 0; i < 64; i++) {
            if (hist[i] > 0) {
                float pb = (float)hist[i] * (1.0f / 64.0f);
                H -= pb * logf(pb);
            }
        }
        if (vmax < 1e-12f) H = 0.0f;
        out[64] = phi2;
        out[65] = H;
    }
}

extern "C" void kernel_launch(void* const* d_in, const int* in_sizes, int n_in,
                              void* d_out, int out_size) {
    (void)in_sizes; (void)n_in; (void)out_size;
    scct_kernel<<<1, 256>>>(
        (const float*)d_in[0],  // u0
        (const float*)d_in[1],  // w1
        (const float*)d_in[2],  // b1
        (const float*)d_in[3],  // w2
        (const float*)d_in[4],  // b2
        (const float*)d_in[5],  // wc
        (const float*)d_in[6],  // bc
        (const float*)d_in[7],  // gamma
        (const int*)  d_in[8],  // Nt
        (float*)d_out);
}